// round 15
// baseline (speedup 1.0000x reference)
#include <cuda_runtime.h>
#include <cuda_fp16.h>

#define NN 50000
#define D  64
#define NE 800000
#define H  128
#define NTILES 391          // 128-row tiles

typedef unsigned int u32;

// Static scratch (no allocs allowed).
__device__ __align__(16) float  g_agg[NN * D];      // (1+eps)*x + scatter sum
__device__ __align__(16) __half g_xh [NN * D];      // x in fp16 (gather source)
// Interleaved MMA B-fragment images: uint2 = (b0,b1) register pair.
// W1: [n=128][kk=4][t=4], n-stride 20 uint2 (16 used + 4 pad)
// W2: [n= 64][kk=8][t=4], n-stride 36 uint2 (32 used + 4 pad)
__device__ __align__(16) uint2 g_w1i[128 * 20];
__device__ __align__(16) uint2 g_w2i[64 * 36];
__device__ int g_idx_is64;

// ---- smem layout (bytes) ----
#define OFF_A1  0            // [128 rows][72 halves], k=64 used  (18432 B)
#define OFF_W1I 18432        // 20480 B
#define OFF_W2I 38912        // 18432 B
#define OFF_SB1 57344        // 128 floats
#define OFF_SB2 57856        // 64 floats
#define SMEM_BYTES 58112

// ---------------------------------------------------------------------------
__device__ __forceinline__ u32 pack_h2(float lo, float hi) {
    __half2 h = __floats2half2_rn(lo, hi);
    return *(u32*)&h;
}
__device__ __forceinline__ void mma_f16(float* c, const u32* a, u32 b0, u32 b1) {
    asm volatile(
        "mma.sync.aligned.m16n8k16.row.col.f32.f16.f16.f32 "
        "{%0,%1,%2,%3}, {%4,%5,%6,%7}, {%8,%9}, {%0,%1,%2,%3};"
        : "+f"(c[0]), "+f"(c[1]), "+f"(c[2]), "+f"(c[3])
        : "r"(a[0]), "r"(a[1]), "r"(a[2]), "r"(a[3]), "r"(b0), "r"(b1));
}
__device__ __forceinline__ u32 smem_u32(const void* p) {
    u32 a;
    asm("{ .reg .u64 t; cvta.to.shared.u64 t, %1; cvt.u32.u64 %0, t; }"
        : "=r"(a) : "l"(p));
    return a;
}
__device__ __forceinline__ void cp16(u32 dst, const void* src) {
    asm volatile("cp.async.cg.shared.global [%0], [%1], 16;"
                 :: "r"(dst), "l"(src) : "memory");
}

// ---------------------------------------------------------------------------
// Kernel 1: g_agg = (1+eps)*x and g_xh = fp16(x) in one pass. Blocks 0-15
// additionally build the interleaved weight-fragment images; block 0 detects
// the edge_index dtype (ids in [0,NN); int32 read as int64 -> >= 2^32 unless
// hi word 0; P(false-pass) ~ (1/NN)^128).
// ---------------------------------------------------------------------------
__global__ void init_kernel(const float* __restrict__ x,
                            const float* __restrict__ eps,
                            const float* __restrict__ W1,
                            const float* __restrict__ W2,
                            const void* __restrict__ ei) {
    int gtid = blockIdx.x * blockDim.x + threadIdx.x;
    if (blockIdx.x == 0 && threadIdx.x < 128) {
        __shared__ int bad;
        if (threadIdx.x == 0) bad = 0;
        __syncthreads();
        long long v = ((const long long*)ei)[threadIdx.x];
        if (v < 0 || v >= NN) atomicOr(&bad, 1);
        __syncthreads();
        if (threadIdx.x == 0) g_idx_is64 = !bad;
    }
    if (gtid < 2048) {                       // W1 fragments: n<128,kk<4,t<4
        int n = gtid >> 4, kk = (gtid >> 2) & 3, t = gtid & 3;
        int k0 = kk * 16 + 2 * t;
        uint2 v;
        v.x = pack_h2(W1[k0 * H + n],       W1[(k0 + 1) * H + n]);
        v.y = pack_h2(W1[(k0 + 8) * H + n], W1[(k0 + 9) * H + n]);
        g_w1i[n * 20 + kk * 4 + t] = v;
    } else if (gtid < 4096) {                // W2 fragments: n<64,kk<8,t<4
        int j = gtid - 2048;
        int n = j >> 5, kk = (j >> 2) & 7, t = j & 3;
        int k0 = kk * 16 + 2 * t;
        uint2 v;
        v.x = pack_h2(W2[k0 * 64 + n],       W2[(k0 + 1) * 64 + n]);
        v.y = pack_h2(W2[(k0 + 8) * 64 + n], W2[(k0 + 9) * 64 + n]);
        g_w2i[n * 36 + kk * 4 + t] = v;
    }
    if (gtid < NN * D / 4) {
        float s = 1.0f + eps[0];
        float4 v = reinterpret_cast<const float4*>(x)[gtid];
        ((uint2*)g_xh)[gtid] = make_uint2(pack_h2(v.x, v.y), pack_h2(v.z, v.w));
        v.x *= s; v.y *= s; v.z *= s; v.w *= s;
        reinterpret_cast<float4*>(g_agg)[gtid] = v;
    }
}

// ---------------------------------------------------------------------------
// Kernel 2: scatter-add. 16 threads/edge (contiguous row), fp16 gather
// (LDG.64), fp32 red.global.add.v4. Grid is an exact multiple -> no guard.
// ---------------------------------------------------------------------------
__global__ void scatter_kernel(const void* __restrict__ ei) {
    int idx = blockIdx.x * blockDim.x + threadIdx.x;
    int e = idx >> 4;
    int c = idx & 15;
    int dst_n, src_n;
    if (g_idx_is64) {
        const long long* p = (const long long*)ei;
        dst_n = (int)p[e];
        src_n = (int)p[NE + e];
    } else {
        const int* p = (const int*)ei;
        dst_n = p[e];
        src_n = p[NE + e];
    }
    uint2 hv = ((const uint2*)(g_xh + (size_t)src_n * D))[c];
    float2 f0 = __half22float2(*(__half2*)&hv.x);
    float2 f1 = __half22float2(*(__half2*)&hv.y);
    float* dst = g_agg + (size_t)dst_n * D + c * 4;
    asm volatile("red.global.add.v4.f32 [%0], {%1, %2, %3, %4};"
                 :: "l"(dst), "f"(f0.x), "f"(f0.y), "f"(f1.x), "f"(f1.y)
                 : "memory");
}

// ---------------------------------------------------------------------------
// Kernel 3: fp16 HMMA MLP. Weights/biases staged via cp.async (no RF
// round-trip, overlaps the A-tile conversion); B fragments read as single
// ld.shared.v2.b32 from the interleaved images.
// ---------------------------------------------------------------------------
__global__ __launch_bounds__(256, 3)
void mlp_kernel(const float* __restrict__ b1, const float* __restrict__ b2,
                float* __restrict__ out) {
    extern __shared__ char sm[];
    u32 sb = smem_u32(sm);
    int tid  = threadIdx.x;
    int wid  = tid >> 5;
    int lane = tid & 31;
    int g = lane >> 2, t = lane & 3;
    int r0 = blockIdx.x * 128;

    // ---- async stage: weights + biases ----
    for (int i = tid; i < 1280; i += 256)
        cp16(sb + OFF_W1I + i * 16, (const char*)g_w1i + i * 16);
    for (int i = tid; i < 1152; i += 256)
        cp16(sb + OFF_W2I + i * 16, (const char*)g_w2i + i * 16);
    if (tid < 32)      cp16(sb + OFF_SB1 + tid * 16, b1 + tid * 4);
    else if (tid < 48) cp16(sb + OFF_SB2 + (tid - 32) * 16, b2 + (tid - 32) * 4);
    asm volatile("cp.async.commit_group;" ::: "memory");

    // ---- manual stage A1: h -> fp16, [row][k] stride 72 halves ----
    for (int f = tid; f < 2048; f += 256) {
        int row = f >> 4, c4 = f & 15;
        int gr = r0 + row; if (gr >= NN) gr = NN - 1;
        float4 av = ((const float4*)g_agg)[gr * 16 + c4];
        char* dst = sm + OFF_A1 + row * 144 + c4 * 8;
        *(u32*)dst       = pack_h2(av.x, av.y);
        *(u32*)(dst + 4) = pack_h2(av.z, av.w);
    }
    asm volatile("cp.async.wait_group 0;" ::: "memory");
    __syncthreads();

    const float* sb1f = (const float*)(sm + OFF_SB1);
    const float* sb2f = (const float*)(sm + OFF_SB2);
    const char* Abase = sm + OFF_A1 + (16 * wid + g) * 144 + 4 * t;

    // ---- phase 1 in two n-halves; phase-2 A fragments built in registers ----
    u32 a2[8][4];
#pragma unroll
    for (int half = 0; half < 2; half++) {
        float acc[8][4];
#pragma unroll
        for (int nt = 0; nt < 8; nt++) {
            int n0 = 64 * half + 8 * nt;
            float bA = sb1f[n0 + 2 * t], bB = sb1f[n0 + 2 * t + 1];
            acc[nt][0] = bA; acc[nt][1] = bB; acc[nt][2] = bA; acc[nt][3] = bB;
        }
#pragma unroll
        for (int kk = 0; kk < 4; kk++) {
            u32 aF[4];
            aF[0] = *(const u32*)(Abase + kk * 32);
            aF[1] = *(const u32*)(Abase + kk * 32 + 1152);
            aF[2] = *(const u32*)(Abase + kk * 32 + 16);
            aF[3] = *(const u32*)(Abase + kk * 32 + 1168);
#pragma unroll
            for (int nt = 0; nt < 8; nt++) {
                uint2 bb = *(const uint2*)(sm + OFF_W1I +
                    (((64 * half + 8 * nt + g) * 20 + kk * 4 + t) << 3));
                mma_f16(acc[nt], aF, bb.x, bb.y);
            }
        }
#pragma unroll
        for (int nt = 0; nt < 8; nt++) {
            float c0 = fmaxf(acc[nt][0], 0.f), c1 = fmaxf(acc[nt][1], 0.f);
            float c2 = fmaxf(acc[nt][2], 0.f), c3 = fmaxf(acc[nt][3], 0.f);
            int kk = 4 * half + (nt >> 1), hf = (nt & 1) * 2;
            a2[kk][hf]     = pack_h2(c0, c1);
            a2[kk][hf + 1] = pack_h2(c2, c3);
        }
    }

    // ---- phase 2 in two n-halves (16 acc regs peak) ----
    int row0 = r0 + 16 * wid + g;
#pragma unroll
    for (int nh = 0; nh < 2; nh++) {
        float acc2[4][4];
#pragma unroll
        for (int nt = 0; nt < 4; nt++) {
            int n0 = 32 * nh + 8 * nt;
            float bA = sb2f[n0 + 2 * t], bB = sb2f[n0 + 2 * t + 1];
            acc2[nt][0] = bA; acc2[nt][1] = bB; acc2[nt][2] = bA; acc2[nt][3] = bB;
        }
#pragma unroll
        for (int kk = 0; kk < 8; kk++) {
#pragma unroll
            for (int nt = 0; nt < 4; nt++) {
                uint2 bb = *(const uint2*)(sm + OFF_W2I +
                    (((32 * nh + 8 * nt + g) * 36 + kk * 4 + t) << 3));
                mma_f16(acc2[nt], a2[kk], bb.x, bb.y);
            }
        }
#pragma unroll
        for (int nt = 0; nt < 4; nt++) {
            int col = 32 * nh + 8 * nt + 2 * t;
            if (row0 < NN) {
                float2 v = { acc2[nt][0], acc2[nt][1] };
                *(float2*)(out + (size_t)row0 * D + col) = v;
            }
            if (row0 + 8 < NN) {
                float2 v = { acc2[nt][2], acc2[nt][3] };
                *(float2*)(out + (size_t)(row0 + 8) * D + col) = v;
            }
        }
    }
}

// ---------------------------------------------------------------------------
extern "C" void kernel_launch(void* const* d_in, const int* in_sizes, int n_in,
                              void* d_out, int out_size) {
    const float* x   = (const float*)d_in[0];
    const void*  ei  = d_in[1];
    const float* W1  = (const float*)d_in[2];
    const float* b1  = (const float*)d_in[3];
    const float* W2  = (const float*)d_in[4];
    const float* b2  = (const float*)d_in[5];
    const float* eps = (const float*)d_in[6];
    float* out = (float*)d_out;

    init_kernel<<<(NN * D / 4 + 255) / 256, 256>>>(x, eps, W1, W2, ei);
    scatter_kernel<<<NE * 16 / 256, 256>>>(ei);

    cudaFuncSetAttribute(mlp_kernel,
                         cudaFuncAttributeMaxDynamicSharedMemorySize, SMEM_BYTES);
    mlp_kernel<<<NTILES, 256, SMEM_BYTES>>>(b1, b2, out);
}

// round 17
// speedup vs baseline: 1.4893x; 1.4893x over previous
#include <cuda_runtime.h>
#include <cuda_fp16.h>

#define NN 50000
#define D  64
#define NE 800000
#define H  128
#define NTILES 391          // 128-row tiles
#define SCAT_BLOCKS (NE * 16 / 256)   // 50000
#define WPREP_BLOCKS 64               // 16384 threads: 8192 W1 + 8192 W2

typedef unsigned int u32;

// Static scratch (no allocs allowed).
__device__ __align__(16) float  g_agg[NN * D];      // (1+eps)*x + scatter sum
__device__ __align__(16) __half g_xh [NN * D];      // x in fp16 (gather source)
__device__ __align__(16) __half g_w1t[128 * 72];    // W1^T padded, smem image
__device__ __align__(16) __half g_w2t[64 * 136];    // W2^T padded, smem image
__device__ int g_idx_is64;

// ---- smem layout (bytes). Stride 144B/272B -> conflict-free fragment LDS
//      (36 / 68 words; both ≡ 4 mod 32 banks across the 8 g-lanes). ----
#define OFF_A1  0            // [128 rows][72 halves], k=64 used   (18432 B)
#define OFF_W1T 18432        // [128 n][72 halves],   k=64 used    (18432 B)
#define OFF_W2T 36864        // [64 n][136 halves],   k=128 used   (17408 B)
#define OFF_SB1 54272        // 128 floats
#define OFF_SB2 54784        // 64 floats
#define SMEM_BYTES 55040

// ---------------------------------------------------------------------------
__device__ __forceinline__ u32 pack_h2(float lo, float hi) {
    __half2 h = __floats2half2_rn(lo, hi);     // x=lo (low half), y=hi
    return *(u32*)&h;
}
__device__ __forceinline__ void mma_f16(float* c, const u32* a, u32 b0, u32 b1) {
    asm volatile(
        "mma.sync.aligned.m16n8k16.row.col.f32.f16.f16.f32 "
        "{%0,%1,%2,%3}, {%4,%5,%6,%7}, {%8,%9}, {%0,%1,%2,%3};"
        : "+f"(c[0]), "+f"(c[1]), "+f"(c[2]), "+f"(c[3])
        : "r"(a[0]), "r"(a[1]), "r"(a[2]), "r"(a[3]), "r"(b0), "r"(b1));
}

// ---------------------------------------------------------------------------
// Kernel 1: g_agg = (1+eps)*x  AND  g_xh = fp16(x), one pass.
// Block 0 also detects edge_index dtype (ids in [0,NN); an int32 buffer read
// as int64 packs two ids -> >= 2^32 unless high word 0; P ~ (1/NN)^128).
// ---------------------------------------------------------------------------
__global__ void init_kernel(const float* __restrict__ x,
                            const float* __restrict__ eps,
                            const void* __restrict__ ei) {
    if (blockIdx.x == 0 && threadIdx.x < 128) {
        __shared__ int bad;
        if (threadIdx.x == 0) bad = 0;
        __syncthreads();
        long long v = ((const long long*)ei)[threadIdx.x];
        if (v < 0 || v >= NN) atomicOr(&bad, 1);
        __syncthreads();
        if (threadIdx.x == 0) g_idx_is64 = !bad;
    }
    int i = blockIdx.x * blockDim.x + threadIdx.x;
    if (i < NN * D / 4) {
        float s = 1.0f + eps[0];
        float4 v = reinterpret_cast<const float4*>(x)[i];
        ((uint2*)g_xh)[i] = make_uint2(pack_h2(v.x, v.y), pack_h2(v.z, v.w));
        v.x *= s; v.y *= s; v.z *= s; v.w *= s;
        reinterpret_cast<float4*>(g_agg)[i] = v;
    }
}

// ---------------------------------------------------------------------------
// Kernel 2: scatter-add (16 threads/edge, fp16 gather LDG.64, fp32
// red.global.add.v4 — the R13 winner). The WPREP_BLOCKS trailing blocks
// (16384 threads: exactly 8192 W1 + 8192 W2 elements) build the fp16
// transposed weight images instead — rides free behind the atomic storm.
// ---------------------------------------------------------------------------
__global__ void scatter_kernel(const void* __restrict__ ei,
                               const float* __restrict__ W1,
                               const float* __restrict__ W2) {
    if (blockIdx.x >= SCAT_BLOCKS) {
        int i = (blockIdx.x - SCAT_BLOCKS) * 256 + threadIdx.x;
        if (i < 64 * H) {                       // W1[k][n], k<64, n<128
            int k = i >> 7, n = i & 127;
            g_w1t[n * 72 + k] = __float2half_rn(W1[i]);
        } else if (i < 64 * H + H * 64) {       // W2[k][n], k<128, n<64
            int j = i - 64 * H;
            int k = j >> 6, n = j & 63;
            g_w2t[n * 136 + k] = __float2half_rn(W2[j]);
        }
        return;
    }
    int idx = blockIdx.x * blockDim.x + threadIdx.x;
    int e = idx >> 4;
    int c = idx & 15;
    int dst_n, src_n;
    if (g_idx_is64) {
        const long long* p = (const long long*)ei;
        dst_n = (int)p[e];
        src_n = (int)p[NE + e];
    } else {
        const int* p = (const int*)ei;
        dst_n = p[e];
        src_n = p[NE + e];
    }
    uint2 hv = ((const uint2*)(g_xh + (size_t)src_n * D))[c];
    float2 f0 = __half22float2(*(__half2*)&hv.x);
    float2 f1 = __half22float2(*(__half2*)&hv.y);
    float* dst = g_agg + (size_t)dst_n * D + c * 4;
    asm volatile("red.global.add.v4.f32 [%0], {%1, %2, %3, %4};"
                 :: "l"(dst), "f"(f0.x), "f"(f0.y), "f"(f1.x), "f"(f1.y)
                 : "memory");
}

// ---------------------------------------------------------------------------
// Kernel 3: fp16 HMMA MLP (R13 winner, unchanged). Phase 2 in two n-halves
// keeps peak regs ~80 -> 3 blocks/SM, single wave. At the legacy-HMMA
// throughput roofline (~144 TF/s fp16 via mma.sync on sm_103).
// ---------------------------------------------------------------------------
__global__ __launch_bounds__(256, 3)
void mlp_kernel(const float* __restrict__ b1, const float* __restrict__ b2,
                float* __restrict__ out) {
    extern __shared__ char sm[];
    int tid  = threadIdx.x;
    int wid  = tid >> 5;
    int lane = tid & 31;
    int g = lane >> 2, t = lane & 3;
    int r0 = blockIdx.x * 128;

    // ---- stage weights: vector copies of the padded images ----
    const uint4* w1g = (const uint4*)g_w1t;
    for (int i = tid; i < 1152; i += 256) ((uint4*)(sm + OFF_W1T))[i] = w1g[i];
    const uint4* w2g = (const uint4*)g_w2t;
    for (int i = tid; i < 1088; i += 256) ((uint4*)(sm + OFF_W2T))[i] = w2g[i];
    if (tid < 128) ((float*)(sm + OFF_SB1))[tid] = b1[tid];
    if (tid < 64)  ((float*)(sm + OFF_SB2))[tid] = b2[tid];

    // ---- stage A1: h -> fp16, [row][k] stride 72 halves ----
    for (int f = tid; f < 2048; f += 256) {
        int row = f >> 4, c4 = f & 15;
        int gr = r0 + row; if (gr >= NN) gr = NN - 1;
        float4 av = ((const float4*)g_agg)[gr * 16 + c4];
        char* dst = sm + OFF_A1 + row * 144 + c4 * 8;
        *(u32*)dst       = pack_h2(av.x, av.y);
        *(u32*)(dst + 4) = pack_h2(av.z, av.w);
    }
    __syncthreads();

    const float* sb1f = (const float*)(sm + OFF_SB1);
    const float* sb2f = (const float*)(sm + OFF_SB2);
    const char* Abase = sm + OFF_A1 + (16 * wid + g) * 144 + 4 * t;

    // ---- phase 1 in two n-halves; phase-2 A fragments built in registers ----
    u32 a2[8][4];
#pragma unroll
    for (int half = 0; half < 2; half++) {
        float acc[8][4];
#pragma unroll
        for (int nt = 0; nt < 8; nt++) {
            int n0 = 64 * half + 8 * nt;
            float bA = sb1f[n0 + 2 * t], bB = sb1f[n0 + 2 * t + 1];
            acc[nt][0] = bA; acc[nt][1] = bB; acc[nt][2] = bA; acc[nt][3] = bB;
        }
#pragma unroll
        for (int kk = 0; kk < 4; kk++) {
            u32 aF[4];
            aF[0] = *(const u32*)(Abase + kk * 32);
            aF[1] = *(const u32*)(Abase + kk * 32 + 1152);
            aF[2] = *(const u32*)(Abase + kk * 32 + 16);
            aF[3] = *(const u32*)(Abase + kk * 32 + 1168);
#pragma unroll
            for (int nt = 0; nt < 8; nt++) {
                const char* Bb = sm + OFF_W1T + (64 * half + 8 * nt + g) * 144
                               + 4 * t + kk * 32;
                mma_f16(acc[nt], aF, *(const u32*)Bb, *(const u32*)(Bb + 16));
            }
        }
#pragma unroll
        for (int nt = 0; nt < 8; nt++) {
            float c0 = fmaxf(acc[nt][0], 0.f), c1 = fmaxf(acc[nt][1], 0.f);
            float c2 = fmaxf(acc[nt][2], 0.f), c3 = fmaxf(acc[nt][3], 0.f);
            int kk = 4 * half + (nt >> 1), hf = (nt & 1) * 2;
            a2[kk][hf]     = pack_h2(c0, c1);
            a2[kk][hf + 1] = pack_h2(c2, c3);
        }
    }

    // ---- phase 2 in two n-halves (16 acc regs peak) ----
    int row0 = r0 + 16 * wid + g;
#pragma unroll
    for (int nh = 0; nh < 2; nh++) {
        float acc2[4][4];
#pragma unroll
        for (int nt = 0; nt < 4; nt++) {
            int n0 = 32 * nh + 8 * nt;
            float bA = sb2f[n0 + 2 * t], bB = sb2f[n0 + 2 * t + 1];
            acc2[nt][0] = bA; acc2[nt][1] = bB; acc2[nt][2] = bA; acc2[nt][3] = bB;
        }
#pragma unroll
        for (int kk = 0; kk < 8; kk++) {
#pragma unroll
            for (int nt = 0; nt < 4; nt++) {
                const char* Bb = sm + OFF_W2T + (32 * nh + 8 * nt + g) * 272
                               + 4 * t + kk * 32;
                mma_f16(acc2[nt], a2[kk], *(const u32*)Bb, *(const u32*)(Bb + 16));
            }
        }
#pragma unroll
        for (int nt = 0; nt < 4; nt++) {
            int col = 32 * nh + 8 * nt + 2 * t;
            if (row0 < NN) {
                float2 v = { acc2[nt][0], acc2[nt][1] };
                *(float2*)(out + (size_t)row0 * D + col) = v;
            }
            if (row0 + 8 < NN) {
                float2 v = { acc2[nt][2], acc2[nt][3] };
                *(float2*)(out + (size_t)(row0 + 8) * D + col) = v;
            }
        }
    }
}

// ---------------------------------------------------------------------------
extern "C" void kernel_launch(void* const* d_in, const int* in_sizes, int n_in,
                              void* d_out, int out_size) {
    const float* x   = (const float*)d_in[0];
    const void*  ei  = d_in[1];
    const float* W1  = (const float*)d_in[2];
    const float* b1  = (const float*)d_in[3];
    const float* W2  = (const float*)d_in[4];
    const float* b2  = (const float*)d_in[5];
    const float* eps = (const float*)d_in[6];
    float* out = (float*)d_out;

    init_kernel<<<(NN * D / 4 + 255) / 256, 256>>>(x, eps, ei);
    scatter_kernel<<<SCAT_BLOCKS + WPREP_BLOCKS, 256>>>(ei, W1, W2);

    cudaFuncSetAttribute(mlp_kernel,
                         cudaFuncAttributeMaxDynamicSharedMemorySize, SMEM_BYTES);
    mlp_kernel<<<NTILES, 256, SMEM_BYTES>>>(b1, b2, out);
}